// round 5
// baseline (speedup 1.0000x reference)
#include <cuda_runtime.h>
#include <math.h>

#define NPTS 4096
#define BITD 64
#define LLAB 10
#define RT   256
#define UPPERB 16.0f
// c = (1/right)*ln(yp/(99(1-yp))) with right=64/6, yp=0.5  -> -6*ln(99)/64
#define CONST_C    (-0.43079248594386178f)
#define CONST_AC   (-0.86158497188772356f)   // a*c, a = 2 exactly
#define CONST_BASE (0.0f)

// ---------------- device scratch ----------------
__device__ float    g_inner[(size_t)NPTS * NPTS];   // 64 MB
__device__ unsigned g_maskArr[NPTS];
__device__ unsigned g_Ybits[LLAB * (NPTS / 32)];    // per-label membership bitvectors
__device__ float2   g_rowout[NPTS];                 // (rowres, valid)
__device__ unsigned g_ctr;

// ---------------- helpers ----------------
__device__ __forceinline__ unsigned fkey(float f) {
    unsigned u = __float_as_uint(f);
    return u ^ (((unsigned)((int)u >> 31)) | 0x80000000u);  // monotonic float->uint
}
__device__ __forceinline__ float finv(unsigned k) {
    unsigned u = (k & 0x80000000u) ? (k ^ 0x80000000u) : ~k;
    return __uint_as_float(u);
}
__device__ __forceinline__ float softplusf(float x) {
    return fmaxf(x, 0.f) + __logf(1.f + __expf(-fabsf(x)));
}

// fused 4-value block reduce (exact for integer-valued floats < 2^24)
__device__ __forceinline__ float4 blockReduce4(float4 v, float4* sh) {
    int tid = threadIdx.x, lane = tid & 31, wid = tid >> 5;
    #pragma unroll
    for (int o = 16; o > 0; o >>= 1) {
        v.x += __shfl_down_sync(0xffffffffu, v.x, o);
        v.y += __shfl_down_sync(0xffffffffu, v.y, o);
        v.z += __shfl_down_sync(0xffffffffu, v.z, o);
        v.w += __shfl_down_sync(0xffffffffu, v.w, o);
    }
    if (lane == 0) sh[wid] = v;
    __syncthreads();
    if (tid == 0) {
        float4 s = sh[0];
        #pragma unroll
        for (int w = 1; w < RT / 32; w++) {
            float4 t = sh[w];
            s.x += t.x; s.y += t.y; s.z += t.z; s.w += t.w;
        }
        sh[0] = s;
    }
    __syncthreads();
    float4 r = sh[0];
    __syncthreads();
    return r;
}

// ---------------- kernel 1: inner = U @ V^T  (+ fused label-mask prep) ----------------
#define TK   32
#define TPAD 36
__global__ void __launch_bounds__(256) gemm_kernel(const float* __restrict__ U,
                                                   const float* __restrict__ V,
                                                   const int* __restrict__ y) {
    if (blockIdx.x == 0 && blockIdx.y == 0) {
        int tid = threadIdx.x, lane = tid & 31;
        #pragma unroll
        for (int it = 0; it < NPTS / 256; it++) {
            int j = it * 256 + tid;
            unsigned m = 0;
            #pragma unroll
            for (int l = 0; l < LLAB; l++) m |= (y[j * LLAB + l] != 0 ? 1u : 0u) << l;
            g_maskArr[j] = m;
            int word = j >> 5;
            #pragma unroll
            for (int b = 0; b < LLAB; b++) {
                unsigned bal = __ballot_sync(0xffffffffu, (m >> b) & 1u);
                if (lane == 0) g_Ybits[b * (NPTS / 32) + word] = bal;
            }
        }
        if (tid == 0) g_ctr = 0;
    }

    __shared__ float As[128][TPAD];
    __shared__ float Bs[128][TPAD];
    int tid = threadIdx.x;
    int tx = tid & 15, ty = tid >> 4;
    int brow = blockIdx.y * 128, bcol = blockIdx.x * 128;
    int lr = tid >> 3;
    int lc4 = tid & 7;

    float acc[8][8];
    #pragma unroll
    for (int i = 0; i < 8; i++)
        #pragma unroll
        for (int j = 0; j < 8; j++) acc[i][j] = 0.f;

    for (int ks = 0; ks < BITD; ks += TK) {
        #pragma unroll
        for (int it = 0; it < 4; it++) {
            int r = it * 32 + lr;
            float4 a = *(const float4*)(U + (size_t)(brow + r) * BITD + ks + lc4 * 4);
            *(float4*)(&As[r][lc4 * 4]) = a;
            float4 b = *(const float4*)(V + (size_t)(bcol + r) * BITD + ks + lc4 * 4);
            *(float4*)(&Bs[r][lc4 * 4]) = b;
        }
        __syncthreads();
        #pragma unroll 4
        for (int k = 0; k < TK; k++) {
            float ar[8], bc[8];
            #pragma unroll
            for (int x = 0; x < 8; x++) ar[x] = As[ty * 8 + x][k];
            #pragma unroll
            for (int x = 0; x < 8; x++) bc[x] = Bs[tx + 16 * x][k];
            #pragma unroll
            for (int i = 0; i < 8; i++)
                #pragma unroll
                for (int j = 0; j < 8; j++) acc[i][j] = fmaf(ar[i], bc[j], acc[i][j]);
        }
        __syncthreads();
    }
    #pragma unroll
    for (int i = 0; i < 8; i++) {
        int row = brow + ty * 8 + i;
        #pragma unroll
        for (int j = 0; j < 8; j++)
            g_inner[(size_t)row * NPTS + bcol + tx + 16 * j] = acc[i][j];
    }
}

// ---------------- dual rank locate on packed histogram ----------------
// hist: NB bins, S count in low 16 bits, D count in high 16 bits.
// Finds for each class the bin containing rank q (1-based) + remaining rank.
template<int NB>
__device__ __forceinline__ void locateDual(const unsigned* hist,
                                           unsigned qS, unsigned qD,
                                           unsigned* wsum,
                                           unsigned* brS, unsigned* brD) {
    const int BPT = NB / RT;
    int tid = threadIdx.x, lane = tid & 31, wid = tid >> 5;
    unsigned s = 0;
    int b0 = tid * BPT;
    #pragma unroll
    for (int t = 0; t < BPT; t++) s += hist[b0 + t];   // packed add (halves < 2^16)
    unsigned v = s;
    #pragma unroll
    for (int o = 1; o < 32; o <<= 1) {
        unsigned t = __shfl_up_sync(0xffffffffu, v, o);
        if (lane >= o) v += t;
    }
    if (lane == 31) wsum[wid] = v;
    __syncthreads();
    unsigned wb = 0;
    #pragma unroll
    for (int w = 0; w < RT / 32; w++) if (w < wid) wb += wsum[w];
    unsigned incl = wb + v, excl = incl - s;
    unsigned inclS = incl & 0xFFFFu, exclS = excl & 0xFFFFu;
    unsigned inclD = incl >> 16,     exclD = excl >> 16;
    if (qS > exclS && qS <= inclS) {
        unsigned c = exclS;
        #pragma unroll
        for (int t = 0; t < BPT; t++) {
            unsigned h = hist[b0 + t] & 0xFFFFu;
            if (qS > c && qS <= c + h) { brS[0] = (unsigned)(b0 + t); brS[1] = qS - c; }
            c += h;
        }
    }
    if (qD > exclD && qD <= inclD) {
        unsigned c = exclD;
        #pragma unroll
        for (int t = 0; t < BPT; t++) {
            unsigned h = hist[b0 + t] >> 16;
            if (qD > c && qD <= c + h) { brD[0] = (unsigned)(b0 + t); brD[1] = qD - c; }
            c += h;
        }
    }
    __syncthreads();
}

// final select: r-th smallest among candidate keys matching top-20-bit prefix.
// cand[lo..hi) in smem; few keys match, so inner loop is entered rarely.
__device__ __forceinline__ void selectFinal(const unsigned* cand, int lo, int hi,
                                            unsigned prefix20, unsigned r,
                                            unsigned* outT) {
    int tid = threadIdx.x;
    for (int idx = lo + tid; idx < hi; idx += RT) {
        unsigned mk = cand[idx];
        if ((mk >> 12) == prefix20) {
            unsigned below = 0, eq = 0;
            for (int j = lo; j < hi; j++) {
                unsigned k = cand[j];
                if ((k >> 12) == prefix20) { below += (k < mk); eq += (k == mk); }
            }
            if (below < r && r <= below + eq) outT[0] = mk;
        }
    }
    __syncthreads();
}

// ---------------- kernel 2: per-row loss (+ fused final reduction) ----------------
__global__ void __launch_bounds__(RT, 5) row_kernel(float* __restrict__ out) {
    __shared__ unsigned hist[4096];     // packed S|D counts; later candidate keys
    __shared__ unsigned subH[256];      // packed sub-bin counts
    __shared__ unsigned wsum[RT / 32];
    __shared__ float4   fsh4[RT / 32];
    __shared__ unsigned brS[2], brD[2];
    __shared__ unsigned candCntS, candCntD;
    __shared__ unsigned TkS, TkD;
    __shared__ int      lastFlag;

    int tid = threadIdx.x, i = blockIdx.x;

    for (int t = tid; t < 4096; t += RT) hist[t] = 0u;
    if (tid < 256) subH[tid] = 0u;
    if (tid == 0) { candCntS = 0u; candCntD = 0u; }

    // class bits for my 16 contiguous elements [tid*16, tid*16+16)
    unsigned mi = g_maskArr[i];
    unsigned cls = 0;
    const unsigned short* yb = (const unsigned short*)g_Ybits;
    #pragma unroll
    for (int b = 0; b < LLAB; b++) {
        unsigned w = (unsigned)yb[b * (NPTS / 16) + tid];
        cls |= w & (0u - ((mi >> b) & 1u));
    }

    // load 16 values, keep only monotonic keys (exact bijection with floats)
    const float* rowp = g_inner + (size_t)i * NPTS + tid * 16;
    float xv[16];
    #pragma unroll
    for (int q = 0; q < 4; q++) {
        float4 f = __ldcs((const float4*)(rowp + q * 4));
        xv[q * 4 + 0] = f.x; xv[q * 4 + 1] = f.y;
        xv[q * 4 + 2] = f.z; xv[q * 4 + 3] = f.w;
    }
    unsigned kk[16];
    float sS = 0.f, sD = 0.f;
    __syncthreads();   // clears done

    // single pass: class sums + packed top-12-bit histogram
    #pragma unroll
    for (int e = 0; e < 16; e++) {
        unsigned k = fkey(xv[e]);
        if ((cls >> e) & 1u) { sS += xv[e]; kk[e] = k; atomicAdd(&hist[k >> 20], 1u); }
        else { sD += xv[e]; k = ~k; kk[e] = k; atomicAdd(&hist[k >> 20], 0x10000u); }
    }
    float4 r0 = blockReduce4(make_float4(sS, sD, (float)__popc(cls), 0.f), fsh4);
    sS = r0.x; sD = r0.y;
    int ns = (int)r0.z, nd = NPTS - ns;

    int ks = (ns * 9) / 10, kd = (nd * 9) / 10;
    unsigned qS = (unsigned)(ns - ks), qD = (unsigned)(nd - kd);
    bool valid = (ns > 0) && (nd > 0);

    float rowres = 0.f;
    if (valid) {
        locateDual<4096>(hist, qS, qD, wsum, brS, brD);
        unsigned b1S = brS[0], r1S = brS[1];
        unsigned b1D = brD[0], r1D = brD[1];

        // candidate compaction (S grows up from 0, D grows down from 4095)
        // + packed 8-bit sub-histogram on bits [12..19]
        #pragma unroll
        for (int e = 0; e < 16; e++) {
            unsigned k = kk[e];
            if ((cls >> e) & 1u) {
                if ((k >> 20) == b1S) {
                    hist[atomicAdd(&candCntS, 1u)] = k;
                    atomicAdd(&subH[(k >> 12) & 255u], 1u);
                }
            } else {
                if ((k >> 20) == b1D) {
                    hist[4095u - atomicAdd(&candCntD, 1u)] = k;
                    atomicAdd(&subH[(k >> 12) & 255u], 0x10000u);
                }
            }
        }
        __syncthreads();
        int cS = (int)candCntS, cD = (int)candCntD;

        locateDual<256>(subH, r1S, r1D, wsum, brS, brD);
        unsigned p20S = (b1S << 8) | brS[0];
        unsigned p20D = (b1D << 8) | brD[0];
        selectFinal(hist, 0, cS, p20S, brS[1], &TkS);
        selectFinal(hist, 4096 - cD, 4096, p20D, brD[1], &TkD);
        unsigned TS = TkS, TD = TkD;

        // exact sums strictly below thresholds (register-only)
        float sLS = 0.f, sLD = 0.f, cLS = 0.f, cLD = 0.f;
        #pragma unroll
        for (int e = 0; e < 16; e++) {
            unsigned k = kk[e];
            if ((cls >> e) & 1u) { if (k < TS) { sLS += xv[e]; cLS += 1.f; } }
            else                 { if (k < TD) { sLD += xv[e]; cLD += 1.f; } }
        }
        float4 r1 = blockReduce4(make_float4(sLS, sLD, cLS, cLD), fsh4);
        float simMinSum = r1.x + ((float)qS - r1.z) * finv(TS);
        float disMaxSum = r1.y + ((float)qD - r1.w) * finv(~TD);

        float similarMin    = simMinSum / (float)max((int)qS, 1);
        float dissimilarMax = disMaxSum / (float)max((int)qD, 1);
        float meanS  = fminf(fmaxf(sS / (float)max(ns, 1), 0.f), UPPERB);
        float meanDS = fminf(fmaxf(sD / (float)max(nd, 1), 0.f), UPPERB);

        float BP   = meanS  - (UPPERB - meanS) / UPPERB * fabsf(meanS - dissimilarMax);
        float BPds = meanDS - meanDS / UPPERB * fabsf(meanDS - similarMin);

        float dcf = CONST_BASE - CONST_C  * BP;
        float gcf = CONST_BASE - CONST_AC * BP;
        float d2  = CONST_BASE - CONST_C  * BPds;
        float g2  = CONST_BASE - CONST_AC * BPds;

        float pos = 0.f, nav = 0.f;
        #pragma unroll
        for (int e = 0; e < 16; e++) {
            float x = xv[e];
            if ((cls >> e) & 1u) {
                float f = (x > BP) ? fmaf(CONST_C, x, dcf) : fmaf(CONST_AC, x, gcf);
                pos += softplusf(f);
            } else {
                float f = (x < BPds) ? fmaf(CONST_C, x, d2) : fmaf(CONST_AC, x, g2);
                nav += softplusf(-f);
            }
        }
        float4 r2 = blockReduce4(make_float4(pos, nav, 0.f, 0.f), fsh4);
        rowres = r2.x / (float)max(ns, 1) + r2.y / (float)max(nd, 1);
    }

    if (tid == 0) {
        g_rowout[i] = make_float2(valid ? rowres : 0.f, valid ? 1.f : 0.f);
        __threadfence();
        unsigned old = atomicAdd(&g_ctr, 1u);
        lastFlag = (old == NPTS - 1) ? 1 : 0;
    }
    __syncthreads();

    if (lastFlag) {
        __threadfence();
        float t = 0.f, c = 0.f;
        for (int idx = tid; idx < NPTS; idx += RT) {
            float2 rv = g_rowout[idx];
            t += rv.x; c += rv.y;
        }
        float4 r3 = blockReduce4(make_float4(t, c, 0.f, 0.f), fsh4);
        if (tid == 0) out[0] = (r3.y > 0.f) ? r3.x / fmaxf(r3.y, 1.f) : 0.f;
    }
}

// ---------------- launch ----------------
extern "C" void kernel_launch(void* const* d_in, const int* in_sizes, int n_in,
                              void* d_out, int out_size) {
    const float* u = (const float*)d_in[0];
    const float* v = (const float*)d_in[1];
    const int*   y = (const int*)d_in[2];

    dim3 gg(NPTS / 128, NPTS / 128);
    gemm_kernel<<<gg, 256>>>(u, v, y);
    row_kernel<<<NPTS, RT>>>((float*)d_out);
}